// round 1
// baseline (speedup 1.0000x reference)
#include <cuda_runtime.h>

#define HH 256
#define WW 256
#define DIM 512
#define NCELL (HH * WW)
#define V4 (DIM / 4)   // 128 float4 per row

// Scratch (device globals — no allocation allowed)
__device__ int   g_map[NCELL];    // cell -> point id, -1 if empty
__device__ int   g_rank[NCELL];   // point id -> output row (only first N used)
__device__ int   g_min[2];
__device__ float g_wT[9 * DIM];   // weights reorganized to [tap][channel]

// ---------------------------------------------------------------------------
__global__ void k_clear() {
    int i = blockIdx.x * blockDim.x + threadIdx.x;
    if (i < NCELL) g_map[i] = -1;
    if (i < 2) g_min[i] = 0x7fffffff;
}

__global__ void k_min(const int* __restrict__ pos, int n) {
    int i = blockIdx.x * blockDim.x + threadIdx.x;
    if (i < n) {
        atomicMin(&g_min[0], pos[2 * i]);
        atomicMin(&g_min[1], pos[2 * i + 1]);
    }
}

__global__ void k_scatter(const int* __restrict__ pos, int n) {
    int i = blockIdx.x * blockDim.x + threadIdx.x;
    if (i < n) {
        int p0 = pos[2 * i]     - g_min[0];
        int p1 = pos[2 * i + 1] - g_min[1];
        g_map[p0 * WW + p1] = i;
    }
}

// Exclusive scan over 65536 cells: rank (output row) per occupied cell's point.
__global__ void k_rank() {
    __shared__ int s[1024];
    int t = threadIdx.x;
    int base = t * 64;
    int cnt = 0;
#pragma unroll 8
    for (int i = 0; i < 64; ++i) cnt += (g_map[base + i] >= 0);
    s[t] = cnt;
    __syncthreads();
    // Hillis-Steele inclusive scan over 1024 entries
    for (int off = 1; off < 1024; off <<= 1) {
        int v = (t >= off) ? s[t - off] : 0;
        __syncthreads();
        if (t >= off) s[t] += v;
        __syncthreads();
    }
    int run = s[t] - cnt;  // exclusive prefix
    for (int i = 0; i < 64; ++i) {
        int m = g_map[base + i];
        if (m >= 0) g_rank[m] = run++;
    }
}

// weight (DIM,1,3,3) -> g_wT[tap*DIM + c], where tap = (dh+1)*3 + (dw+1)
// and coefficient for offset (dh,dw) is weight[c][0][dw+1][dh+1]  (transposed
// spatial axes because xd = grid.transpose(2,1,0)).
__global__ void k_wT(const float* __restrict__ w) {
    int i = blockIdx.x * blockDim.x + threadIdx.x;
    if (i < 9 * DIM) {
        int tap = i / DIM, c = i % DIM;
        int dh = tap / 3 - 1, dw = tap % 3 - 1;
        g_wT[i] = w[c * 9 + (dw + 1) * 3 + (dh + 1)];
    }
}

// One block per point; 128 threads, each handles 4 channels (float4).
__global__ void __launch_bounds__(128) k_main(
    const float4* __restrict__ x4,
    const int*    __restrict__ pos,
    const float4* __restrict__ bias4,
    float4*       __restrict__ out4)
{
    __shared__ int nbr[9];
    __shared__ int srank;
    const int n = blockIdx.x;
    const int t = threadIdx.x;

    if (t < 9) {
        int p0 = pos[2 * n]     - g_min[0];
        int p1 = pos[2 * n + 1] - g_min[1];
        int h = p0 + t / 3 - 1;
        int w = p1 + t % 3 - 1;
        nbr[t] = (h >= 0 && h < HH && w >= 0 && w < WW) ? g_map[h * WW + w] : -1;
        if (t == 0) srank = g_rank[n];
    }
    __syncthreads();

    float4 acc = x4[(size_t)n * V4 + t];     // residual (+xd term)
    float4 b   = bias4[t];
    acc.x += b.x; acc.y += b.y; acc.z += b.z; acc.w += b.w;

    const float4* wT4 = (const float4*)g_wT;
#pragma unroll
    for (int tap = 0; tap < 9; ++tap) {
        int m = nbr[tap];                    // uniform across block: no divergence
        if (m >= 0) {
            float4 v  = x4[(size_t)m * V4 + t];
            float4 wv = wT4[tap * V4 + t];
            acc.x = fmaf(wv.x, v.x, acc.x);
            acc.y = fmaf(wv.y, v.y, acc.y);
            acc.z = fmaf(wv.z, v.z, acc.z);
            acc.w = fmaf(wv.w, v.w, acc.w);
        }
    }
    out4[(size_t)srank * V4 + t] = acc;
}

// ---------------------------------------------------------------------------
extern "C" void kernel_launch(void* const* d_in, const int* in_sizes, int n_in,
                              void* d_out, int out_size) {
    const float* x    = (const float*)d_in[0];   // (1, N, 512) f32
    const int*   pos  = (const int*)  d_in[1];   // (N, 2) i32
    const float* w    = (const float*)d_in[2];   // (512,1,3,3) f32
    const float* bias = (const float*)d_in[3];   // (512,) f32
    float*       out  = (float*)d_out;           // (1, N, 512) f32

    const int n = in_sizes[1] / 2;

    k_clear  <<<(NCELL + 255) / 256, 256>>>();
    k_min    <<<(n + 255) / 256, 256>>>(pos, n);
    k_scatter<<<(n + 255) / 256, 256>>>(pos, n);
    k_rank   <<<1, 1024>>>();
    k_wT     <<<(9 * DIM + 255) / 256, 256>>>(w);
    k_main   <<<n, 128>>>((const float4*)x, pos, (const float4*)bias,
                          (float4*)out);
}

// round 2
// speedup vs baseline: 2.9532x; 2.9532x over previous
#include <cuda_runtime.h>

#define HH 256
#define WW 256
#define DIM 512
#define NCELL (HH * WW)
#define V4 (DIM / 4)   // 128 float4 per row

// Scratch (device globals — no allocation allowed)
__device__ int   g_map[NCELL];    // cell -> point id, -1 if empty
__device__ int   g_rank[NCELL];   // point id -> output row (only first N used)
__device__ int   g_min[2];
__device__ float g_wT[9 * DIM];   // weights reorganized to [tap][channel]
__device__ int   g_bsum[256];     // per-block occupancy counts
__device__ int   g_boff[256];     // exclusive prefix of g_bsum

// ---------------------------------------------------------------------------
// Fused init: clear map, init mins, transpose weights.
// weight (DIM,1,3,3) -> g_wT[tap*DIM + c], tap = (dh+1)*3 + (dw+1); the
// coefficient for spatial offset (dh,dw) is weight[c][0][dw+1][dh+1]
// (spatial axes transposed because xd = grid.transpose(2,1,0)).
__global__ void k_init(const float* __restrict__ w) {
    int i = blockIdx.x * blockDim.x + threadIdx.x;
    if (i < NCELL) g_map[i] = -1;
    if (i < 2) g_min[i] = 0x7fffffff;
    if (i < 9 * DIM) {
        int tap = i / DIM, c = i % DIM;
        int dh = tap / 3 - 1, dw = tap % 3 - 1;
        g_wT[i] = w[c * 9 + (dw + 1) * 3 + (dh + 1)];
    }
}

__global__ void k_min(const int* __restrict__ pos, int n) {
    int i = blockIdx.x * blockDim.x + threadIdx.x;
    if (i < n) {
        atomicMin(&g_min[0], pos[2 * i]);
        atomicMin(&g_min[1], pos[2 * i + 1]);
    }
}

__global__ void k_scatter(const int* __restrict__ pos, int n) {
    int i = blockIdx.x * blockDim.x + threadIdx.x;
    if (i < n) {
        int p0 = pos[2 * i]     - g_min[0];
        int p1 = pos[2 * i + 1] - g_min[1];
        g_map[p0 * WW + p1] = i;
    }
}

// ---- 3-phase chip-wide exclusive scan over the occupancy bitmap ----------
__global__ void k_scanA() {
    int t = threadIdx.x;
    int i = blockIdx.x * 256 + t;
    unsigned bal = __ballot_sync(0xffffffffu, g_map[i] >= 0);
    __shared__ int ws[8];
    if ((t & 31) == 0) ws[t >> 5] = __popc(bal);
    __syncthreads();
    if (t == 0) {
        int s = 0;
#pragma unroll
        for (int w = 0; w < 8; ++w) s += ws[w];
        g_bsum[blockIdx.x] = s;
    }
}

__global__ void k_scanB() {
    __shared__ int s[256];
    int t = threadIdx.x;
    int mine = g_bsum[t];
    s[t] = mine;
    __syncthreads();
    for (int off = 1; off < 256; off <<= 1) {
        int v = (t >= off) ? s[t - off] : 0;
        __syncthreads();
        s[t] += v;
        __syncthreads();
    }
    g_boff[t] = s[t] - mine;   // exclusive prefix
}

__global__ void k_scanC() {
    int t = threadIdx.x;
    int i = blockIdx.x * 256 + t;
    int m = g_map[i];
    unsigned bal = __ballot_sync(0xffffffffu, m >= 0);
    int lane = t & 31, wid = t >> 5;
    int intra = __popc(bal & ((1u << lane) - 1));
    __shared__ int woff[8];
    __shared__ int ws[8];
    if (lane == 0) ws[wid] = __popc(bal);
    __syncthreads();
    if (t == 0) {
        int s = 0;
#pragma unroll
        for (int w = 0; w < 8; ++w) { woff[w] = s; s += ws[w]; }
    }
    __syncthreads();
    if (m >= 0) g_rank[m] = g_boff[blockIdx.x] + woff[wid] + intra;
}

// ---------------------------------------------------------------------------
// One block per point; 128 threads, each handles 4 channels (float4).
__global__ void __launch_bounds__(128) k_main(
    const float4* __restrict__ x4,
    const int*    __restrict__ pos,
    const float4* __restrict__ bias4,
    float4*       __restrict__ out4)
{
    __shared__ int nbr[9];
    __shared__ int srank;
    const int n = blockIdx.x;
    const int t = threadIdx.x;

    if (t < 9) {
        int p0 = pos[2 * n]     - g_min[0];
        int p1 = pos[2 * n + 1] - g_min[1];
        int h = p0 + t / 3 - 1;
        int w = p1 + t % 3 - 1;
        nbr[t] = (h >= 0 && h < HH && w >= 0 && w < WW) ? g_map[h * WW + w] : -1;
        if (t == 0) srank = g_rank[n];
    }
    __syncthreads();

    float4 acc = x4[(size_t)n * V4 + t];     // residual (+xd term)
    float4 b   = bias4[t];
    acc.x += b.x; acc.y += b.y; acc.z += b.z; acc.w += b.w;

    const float4* wT4 = (const float4*)g_wT;
#pragma unroll
    for (int tap = 0; tap < 9; ++tap) {
        int m = nbr[tap];                    // uniform across block: no divergence
        if (m >= 0) {
            float4 v  = x4[(size_t)m * V4 + t];
            float4 wv = wT4[tap * V4 + t];
            acc.x = fmaf(wv.x, v.x, acc.x);
            acc.y = fmaf(wv.y, v.y, acc.y);
            acc.z = fmaf(wv.z, v.z, acc.z);
            acc.w = fmaf(wv.w, v.w, acc.w);
        }
    }
    out4[(size_t)srank * V4 + t] = acc;
}

// ---------------------------------------------------------------------------
extern "C" void kernel_launch(void* const* d_in, const int* in_sizes, int n_in,
                              void* d_out, int out_size) {
    const float* x    = (const float*)d_in[0];   // (1, N, 512) f32
    const int*   pos  = (const int*)  d_in[1];   // (N, 2) i32
    const float* w    = (const float*)d_in[2];   // (512,1,3,3) f32
    const float* bias = (const float*)d_in[3];   // (512,) f32
    float*       out  = (float*)d_out;           // (1, N, 512) f32

    const int n = in_sizes[1] / 2;

    k_init   <<<(NCELL + 255) / 256, 256>>>(w);
    k_min    <<<(n + 255) / 256, 256>>>(pos, n);
    k_scatter<<<(n + 255) / 256, 256>>>(pos, n);
    k_scanA  <<<256, 256>>>();
    k_scanB  <<<1, 256>>>();
    k_scanC  <<<256, 256>>>();
    k_main   <<<n, 128>>>((const float4*)x, pos, (const float4*)bias,
                          (float4*)out);
}